// round 12
// baseline (speedup 1.0000x reference)
#include <cuda_runtime.h>
#include <cuda_bf16.h>
#include <cstdint>
#include <cstring>
#include <math.h>

#define D 128
#define MAX_NDST 50000
#define MAX_NSRC 100000
#define MAX_E    600000

// Scratch (static device globals -- no allocation allowed)
__device__ __align__(16) float g_a_dst[MAX_NDST * D];            // feat_dst @ W1h^T + b1
__device__ __align__(16) __nv_bfloat16 g_b_src_h[MAX_NSRC * D];  // bf16(feat_src @ W1m^T)
__device__ __align__(16) float g_neigh[MAX_NDST * D];            // aggregation
__device__ __align__(16) __nv_bfloat16 g_wh[2 * 128 * 256];      // W1|Wfc hi bf16
__device__ __align__(16) __nv_bfloat16 g_wl[2 * 128 * 256];      // W1|Wfc lo bf16
__device__ int g_cnt[MAX_NDST];
__device__ int g_off[MAX_NDST + 1];
__device__ int g_cur[MAX_NDST];
__device__ int g_srcs[MAX_E];

// ---------------------------------------------------------------------------
// helpers
// ---------------------------------------------------------------------------
__device__ __forceinline__ float tanha(float x) {
    float y;
    asm("tanh.approx.f32 %0, %1;" : "=f"(y) : "f"(x));
    return y;
}

__device__ __forceinline__ uint32_t s2u(const void* p) {
    uint32_t a;
    asm("{ .reg .u64 t; cvta.to.shared.u64 t, %1; cvt.u32.u64 %0, t; }"
        : "=r"(a) : "l"(p));
    return a;
}

__device__ __forceinline__ void ldsm_x4(uint32_t* r, uint32_t addr) {
    asm volatile("ldmatrix.sync.aligned.m8n8.x4.shared.b16 {%0,%1,%2,%3}, [%4];"
        : "=r"(r[0]), "=r"(r[1]), "=r"(r[2]), "=r"(r[3]) : "r"(addr));
}

// D[16x8] += A[16x16] * B[16x8] (bf16 in, fp32 acc)
__device__ __forceinline__ void mma16816(float* c, const uint32_t* a, const uint32_t* b) {
    asm volatile("mma.sync.aligned.m16n8k16.row.col.f32.bf16.bf16.f32 "
        "{%0,%1,%2,%3}, {%4,%5,%6,%7}, {%8,%9}, {%0,%1,%2,%3};"
        : "+f"(c[0]), "+f"(c[1]), "+f"(c[2]), "+f"(c[3])
        : "r"(a[0]), "r"(a[1]), "r"(a[2]), "r"(a[3]), "r"(b[0]), "r"(b[1]));
}

__device__ __forceinline__ uint32_t pack_bf16(float a, float b) {
    __nv_bfloat162 t = __floats2bfloat162_rn(a, b);
    uint32_t r;
    memcpy(&r, &t, 4);
    return r;
}

__device__ __forceinline__ uint32_t pack2h(__nv_bfloat16 a, __nv_bfloat16 b) {
    uint16_t ua, ub;
    memcpy(&ua, &a, 2);
    memcpy(&ub, &b, 2);
    return (uint32_t)ua | ((uint32_t)ub << 16);
}

__device__ __forceinline__ int warp_incl_scan(int v, int lane) {
#pragma unroll
    for (int o = 1; o < 32; o <<= 1) {
        int t = __shfl_up_sync(0xFFFFFFFFu, v, o);
        if (lane >= o) v += t;
    }
    return v;
}

// ---------------------------------------------------------------------------
// init: W fp32->bf16(hi,lo) precompute + zero degree counters (one launch)
// ---------------------------------------------------------------------------
__global__ void init_kernel(const float* __restrict__ W1,
                            const float* __restrict__ Wfc, int ndst) {
    int i = blockIdx.x * blockDim.x + threadIdx.x;
    if (i < 2 * 128 * 256) {
        float w = (i < 128 * 256) ? W1[i] : Wfc[i - 128 * 256];
        __nv_bfloat16 h = __float2bfloat16_rn(w);
        g_wh[i] = h;
        g_wl[i] = __float2bfloat16_rn(w - __bfloat162float(h));
    }
    if (i < ndst) g_cnt[i] = 0;
}

__global__ void count_kernel(const int* __restrict__ ed, int E) {
    int e = blockIdx.x * blockDim.x + threadIdx.x;
    if (e < E) atomicAdd(&g_cnt[ed[e]], 1);
}

// ---------------------------------------------------------------------------
// Single-block exclusive scan of g_cnt -> g_off, g_cur (replaces 3 kernels).
// 1024 threads x 4 elements per iteration, sequential carry.
// ---------------------------------------------------------------------------
#define SCT 1024
__global__ void __launch_bounds__(SCT) scan_all_kernel(int n, int E) {
    __shared__ int wsum[32];
    __shared__ int carry_s;
    int tid = threadIdx.x, lane = tid & 31, wid = tid >> 5;
    int carry = 0;
    for (int base = 0; base < n; base += SCT * 4) {
        int idx = base + tid * 4;
        int v0 = 0, v1 = 0, v2 = 0, v3 = 0;
        if (idx + 3 < n) {
            int4 t = *(const int4*)&g_cnt[idx];
            v0 = t.x; v1 = t.y; v2 = t.z; v3 = t.w;
        } else {
            if (idx     < n) v0 = g_cnt[idx];
            if (idx + 1 < n) v1 = g_cnt[idx + 1];
            if (idx + 2 < n) v2 = g_cnt[idx + 2];
            if (idx + 3 < n) v3 = g_cnt[idx + 3];
        }
        int s = v0 + v1 + v2 + v3;
        int incl = warp_incl_scan(s, lane);
        if (lane == 31) wsum[wid] = incl;
        __syncthreads();
        if (wid == 0) {
            int t = wsum[lane];
            int ti = warp_incl_scan(t, lane);
            wsum[lane] = ti - t;
        }
        __syncthreads();
        int excl = incl - s + wsum[wid] + carry;
        if (idx     < n) { g_off[idx]     = excl;             g_cur[idx]     = excl; }
        if (idx + 1 < n) { int e1 = excl + v0;           g_off[idx + 1] = e1; g_cur[idx + 1] = e1; }
        if (idx + 2 < n) { int e2 = excl + v0 + v1;      g_off[idx + 2] = e2; g_cur[idx + 2] = e2; }
        if (idx + 3 < n) { int e3 = excl + v0 + v1 + v2; g_off[idx + 3] = e3; g_cur[idx + 3] = e3; }
        if (tid == SCT - 1) carry_s = excl + s;
        __syncthreads();
        carry = carry_s;
    }
    if (tid == 0) g_off[n] = E;
}

__global__ void scatter_kernel(const int* __restrict__ es,
                               const int* __restrict__ ed, int E) {
    int e = blockIdx.x * blockDim.x + threadIdx.x;
    if (e < E) {
        int pos = atomicAdd(&g_cur[ed[e]], 1);
        g_srcs[pos] = es[e];
    }
}

// ---------------------------------------------------------------------------
// HMMA bf16 split GEMM (mma.sync m16n8k16):
//   C[m, n] = act( sum_k A[m,k] * W[n, wbase+k] + bias[n] ),  n in [0,128)
//   A: fp32 -> (hi, lo) bf16 per block; W: precomputed bf16 (Wh, Wl).
//   D += Ah*Bh + Al*Bh + Ah*Bl  (fp32 reg accumulate)
//   OBF16: write bf16 output (for the b_src table).
// Block: 256 threads = 8 warps (4 M x 2 N), tile 128x128, K chunked by 64.
// ---------------------------------------------------------------------------
#define LDSB   144                 // bytes per smem tile row (72 bf16)
#define TILEB  (128 * LDSB)        // 18432
#define OFF_AH 0
#define OFF_AL TILEB
#define OFF_BH (2 * TILEB)
#define OFF_BL (3 * TILEB)
#define SMEM_SZ (4 * TILEB)        // 73728

template <bool TWO, bool RELU, bool OBF16>
__global__ void __launch_bounds__(256) mma_gemm_kernel(
    const float* __restrict__ A1,
    const float* __restrict__ A2,
    const __nv_bfloat16* __restrict__ Wh,
    const __nv_bfloat16* __restrict__ Wl,
    int ldw, int wbase,
    const float* __restrict__ bias,
    void* __restrict__ Cv, int M)
{
    extern __shared__ char smem[];
    const uint32_t sb = s2u(smem);
    const int tid  = threadIdx.x;
    const int warp = tid >> 5;
    const int lane = tid & 31;
    const int wm   = (warp & 3) * 32;
    const int wn   = (warp >> 2) * 64;
    const int m0   = blockIdx.x * 128;

    float acc[2][8][4];
#pragma unroll
    for (int mf = 0; mf < 2; mf++)
#pragma unroll
        for (int nf = 0; nf < 8; nf++)
#pragma unroll
            for (int j = 0; j < 4; j++) acc[mf][nf][j] = 0.0f;

    const int nch = TWO ? 4 : 2;
    for (int ch = 0; ch < nch; ch++) {
        const float* Ap = (TWO && ch >= 2) ? A2 : A1;
        const int ak0 = TWO ? ((ch & 1) * 64) : ch * 64;
        const int wk0 = wbase + ch * 64;

        if (ch > 0) __syncthreads();

        // --- convert A tile: 128 rows x 64 cols fp32 -> bf16 hi/lo ---
#pragma unroll
        for (int t = 0; t < 8; t++) {
            int slot = tid + t * 256;
            int row  = slot >> 4;
            int c4   = slot & 15;
            int m = m0 + row;
            if (m >= M) m = M - 1;
            float4 v = *(const float4*)(Ap + (size_t)m * D + ak0 + c4 * 4);
            __nv_bfloat16 h0 = __float2bfloat16_rn(v.x);
            __nv_bfloat16 h1 = __float2bfloat16_rn(v.y);
            __nv_bfloat16 h2 = __float2bfloat16_rn(v.z);
            __nv_bfloat16 h3 = __float2bfloat16_rn(v.w);
            uint32_t off = row * LDSB + c4 * 8;
            *(uint2*)(smem + OFF_AH + off) =
                make_uint2(pack2h(h0, h1), pack2h(h2, h3));
            *(uint2*)(smem + OFF_AL + off) =
                make_uint2(pack_bf16(v.x - __bfloat162float(h0), v.y - __bfloat162float(h1)),
                           pack_bf16(v.z - __bfloat162float(h2), v.w - __bfloat162float(h3)));
        }
        // --- copy B tile (precomputed bf16) ---
#pragma unroll
        for (int t = 0; t < 4; t++) {
            int slot = tid + t * 256;
            int row  = slot >> 3;
            int c8   = slot & 7;
            uint32_t off = row * LDSB + c8 * 16;
            *(uint4*)(smem + OFF_BH + off) =
                *(const uint4*)(Wh + (size_t)row * ldw + wk0 + c8 * 8);
            *(uint4*)(smem + OFF_BL + off) =
                *(const uint4*)(Wl + (size_t)row * ldw + wk0 + c8 * 8);
        }
        __syncthreads();

        // --- mma over 4 k16-steps ---
#pragma unroll
        for (int ks = 0; ks < 4; ks++) {
            uint32_t ah[2][4], al[2][4];
            {
                uint32_t off = (uint32_t)(wm + (lane & 15)) * LDSB
                             + (ks * 16 + (lane >> 4) * 8) * 2;
#pragma unroll
                for (int mf = 0; mf < 2; mf++) {
                    ldsm_x4(ah[mf], sb + OFF_AH + off + mf * 16 * LDSB);
                    ldsm_x4(al[mf], sb + OFF_AL + off + mf * 16 * LDSB);
                }
            }
            uint32_t boff;
            {
                int i = lane >> 3;
                int r = (i >> 1) * 8 + (lane & 7);
                int h = i & 1;
                boff = (uint32_t)(wn + r) * LDSB + (ks * 16 + h * 8) * 2;
            }
#pragma unroll
            for (int p = 0; p < 4; p++) {
                uint32_t bh[4], bl[4];
                ldsm_x4(bh, sb + OFF_BH + boff + p * 16 * LDSB);
                ldsm_x4(bl, sb + OFF_BL + boff + p * 16 * LDSB);
#pragma unroll
                for (int mf = 0; mf < 2; mf++) {
                    mma16816(acc[mf][2 * p],     ah[mf], &bh[0]);
                    mma16816(acc[mf][2 * p + 1], ah[mf], &bh[2]);
                    mma16816(acc[mf][2 * p],     al[mf], &bh[0]);
                    mma16816(acc[mf][2 * p + 1], al[mf], &bh[2]);
                    mma16816(acc[mf][2 * p],     ah[mf], &bl[0]);
                    mma16816(acc[mf][2 * p + 1], ah[mf], &bl[2]);
                }
            }
        }
    }

    // --- epilogue ---
#pragma unroll
    for (int mf = 0; mf < 2; mf++) {
#pragma unroll
        for (int nf = 0; nf < 8; nf++) {
            int n = wn + nf * 8 + (lane & 3) * 2;
            float bx = 0.f, by = 0.f;
            if (bias) {
                float2 bv = *(const float2*)(bias + n);
                bx = bv.x; by = bv.y;
            }
            int mrow = m0 + wm + mf * 16 + (lane >> 2);
            float* c = acc[mf][nf];
#pragma unroll
            for (int half = 0; half < 2; half++) {
                int m = mrow + half * 8;
                if (m < M) {
                    float ox = c[half * 2]     + bx;
                    float oy = c[half * 2 + 1] + by;
                    if (RELU) { ox = fmaxf(ox, 0.f); oy = fmaxf(oy, 0.f); }
                    if (OBF16) {
                        *(uint32_t*)((__nv_bfloat16*)Cv + (size_t)m * D + n) =
                            pack_bf16(ox, oy);
                    } else {
                        float2 o; o.x = ox; o.y = oy;
                        *(float2*)((float*)Cv + (size_t)m * D + n) = o;
                    }
                }
            }
        }
    }
}

// ---------------------------------------------------------------------------
// Fused attention: one warp per dst, single CSR pass. b_src gathered as bf16
// (score path only -- aggregation values stay fp32).
// ---------------------------------------------------------------------------
__global__ void __launch_bounds__(256) fused_attn_kernel(
    const float* __restrict__ feat_src,
    const float* __restrict__ W2,
    const float* __restrict__ b2,
    int ndst)
{
    int w    = (blockIdx.x * blockDim.x + threadIdx.x) >> 5;
    int lane = threadIdx.x & 31;
    if (w >= ndst) return;

    int beg = g_off[w];
    int end = g_off[w + 1];
    float4* nrow = (float4*)(g_neigh + (size_t)w * D);

    if (beg == end) {
        nrow[lane] = make_float4(0.f, 0.f, 0.f, 0.f);
        return;
    }

    float4 ad = ((const float4*)(g_a_dst + (size_t)w * D))[lane];
    float4 w2 = ((const float4*)W2)[lane];
    float b2v = b2[0];

    float denom = 0.0f;
    float4 acc = make_float4(0.f, 0.f, 0.f, 0.f);

    int s = __ldg(&g_srcs[beg]);
    for (int i = beg; i < end; i++) {
        int s_next = (i + 1 < end) ? __ldg(&g_srcs[i + 1]) : 0;
        uint2 bsu = ((const uint2*)(g_b_src_h + (size_t)s * D))[lane];
        float4 m  = ((const float4*)(feat_src + (size_t)s * D))[lane];
        __nv_bfloat162 bp0, bp1;
        memcpy(&bp0, &bsu.x, 4);
        memcpy(&bp1, &bsu.y, 4);
        float2 b0 = __bfloat1622float2(bp0);
        float2 b1 = __bfloat1622float2(bp1);

        float p = tanha(ad.x + b0.x) * w2.x
                + tanha(ad.y + b0.y) * w2.y
                + tanha(ad.z + b1.x) * w2.z
                + tanha(ad.w + b1.y) * w2.w;
#pragma unroll
        for (int o = 16; o; o >>= 1) p += __shfl_xor_sync(0xFFFFFFFFu, p, o);

        float ex = __expf(p + b2v);
        denom += ex;
        acc.x = fmaf(ex, m.x, acc.x);
        acc.y = fmaf(ex, m.y, acc.y);
        acc.z = fmaf(ex, m.z, acc.z);
        acc.w = fmaf(ex, m.w, acc.w);
        s = s_next;
    }

    float inv = 1.0f / denom;
    acc.x *= inv; acc.y *= inv; acc.z *= inv; acc.w *= inv;
    nrow[lane] = acc;
}

// ---------------------------------------------------------------------------
// Launcher
// ---------------------------------------------------------------------------
extern "C" void kernel_launch(void* const* d_in, const int* in_sizes, int n_in,
                              void* d_out, int out_size)
{
    const float* feat_src = (const float*)d_in[0];
    const float* feat_dst = (const float*)d_in[1];
    const float* W1       = (const float*)d_in[2];
    const float* b1       = (const float*)d_in[3];
    const float* W2       = (const float*)d_in[4];
    const float* b2       = (const float*)d_in[5];
    const float* Wfc      = (const float*)d_in[6];
    const float* bfc      = (const float*)d_in[7];
    const int*   es       = (const int*)d_in[8];
    const int*   ed       = (const int*)d_in[9];

    const int NSRC = in_sizes[0] / D;
    const int NDST = in_sizes[1] / D;
    const int E    = in_sizes[8];

    void *p_a, *p_bh, *p_n, *p_wh, *p_wl;
    cudaGetSymbolAddress(&p_a, g_a_dst);
    cudaGetSymbolAddress(&p_bh, g_b_src_h);
    cudaGetSymbolAddress(&p_n, g_neigh);
    cudaGetSymbolAddress(&p_wh, g_wh);
    cudaGetSymbolAddress(&p_wl, g_wl);
    float* a_dst = (float*)p_a;
    float* neigh = (float*)p_n;
    const __nv_bfloat16* wh = (const __nv_bfloat16*)p_wh;
    const __nv_bfloat16* wl = (const __nv_bfloat16*)p_wl;

    cudaFuncSetAttribute(mma_gemm_kernel<false, false, false>,
                         cudaFuncAttributeMaxDynamicSharedMemorySize, SMEM_SZ);
    cudaFuncSetAttribute(mma_gemm_kernel<false, false, true>,
                         cudaFuncAttributeMaxDynamicSharedMemorySize, SMEM_SZ);
    cudaFuncSetAttribute(mma_gemm_kernel<true, true, false>,
                         cudaFuncAttributeMaxDynamicSharedMemorySize, SMEM_SZ);

    // --- init: W bf16 precompute + zero counters ---
    init_kernel<<<(2 * 128 * 256 + 255) / 256, 256>>>(W1, Wfc, NDST);

    // --- CSR build (count -> single-kernel scan -> scatter) ---
    count_kernel<<<(E + 255) / 256, 256>>>(ed, E);
    scan_all_kernel<<<1, SCT>>>(NDST, E);
    scatter_kernel<<<(E + 255) / 256, 256>>>(es, ed, E);

    // --- node GEMMs (HMMA bf16 split, precomputed W) ---
    mma_gemm_kernel<false, false, false><<<(NDST + 127) / 128, 256, SMEM_SZ>>>(
        feat_dst, nullptr, wh, wl, 2 * D, 0, b1, a_dst, NDST);
    mma_gemm_kernel<false, false, true><<<(NSRC + 127) / 128, 256, SMEM_SZ>>>(
        feat_src, nullptr, wh, wl, 2 * D, D, nullptr, p_bh, NSRC);

    // --- fused edge softmax + aggregation ---
    fused_attn_kernel<<<(NDST * 32 + 255) / 256, 256>>>(feat_src, W2, b2, NDST);

    // --- out = relu( [feat_dst, neigh] @ Wfc^T + bfc ) ---
    mma_gemm_kernel<true, true, false><<<(NDST + 127) / 128, 256, SMEM_SZ>>>(
        feat_dst, neigh, wh + 128 * 256, wl + 128 * 256, 2 * D, 0, bfc, d_out, NDST);
}